// round 1
// baseline (speedup 1.0000x reference)
#include <cuda_runtime.h>
#include <math.h>

// ---------------- problem constants ----------------
#define NF      32          // B*S frames
#define C       64
#define H       96
#define W       96
#define P       6
#define PR      16          // patches per row
#define NPATCH  256         // PR*PR
#define FEAT    2304        // C*P*P
#define DIM     768
#define M_TOK   (NF*NPATCH)                 // 8192
#define TOK_ELEMS   (M_TOK*DIM)             // 6291456
#define PATCH_ELEMS (M_TOK*FEAT)            // 18874368
#define FRAME_STRIDE (C*H*W)                // 589824

// conv+bn+gelu activation scratch (allocation-free: __device__ global)
__device__ float g_y[NF*C*H*W];

__device__ __forceinline__ float gelu_exact(float x){
    return 0.5f*x*(1.0f + erff(x*0.7071067811865476f));
}

// =====================================================================
// Kernel 1: 3x3 conv (pad 1) + bias + BN(eval) + exact GELU -> g_y
// Block: 256 threads. Tile: 32(x) * 8(y) spatial, 16 c_out.
// Thread: 4 c_out * 4 x-pixels, 1 y-row => 16 accumulators.
// Per c_in step: 144 FFMA vs ~54 LDS per thread -> FFMA-bound.
// =====================================================================
__global__ __launch_bounds__(256, 2) void conv_bn_gelu_kernel(
    const float* __restrict__ x,
    const float* __restrict__ cw,
    const float* __restrict__ cb,
    const float* __restrict__ gamma,
    const float* __restrict__ beta,
    const float* __restrict__ mean,
    const float* __restrict__ var)
{
    __shared__ float s_in[10][36];   // rows y0-1..y0+8, cols x0-1..x0+32 (34 used)
    __shared__ float s_w[16][9];     // 16 c_out x 9 taps for current c_in

    const int tid = threadIdx.x;
    const int tc  = tid & 3;         // c_out sub-group (4 c_out each)
    const int tx  = (tid >> 2) & 7;  // x sub-tile (4 px each)
    const int ty  = tid >> 5;        // y row (0..7)

    const int bx    = blockIdx.x;        // 0..2
    const int by    = blockIdx.y;        // 0..11
    const int frame = blockIdx.z >> 2;   // 0..31
    const int cog   = blockIdx.z & 3;    // 0..3 (c_out group of 16)
    const int co_base = cog*16 + tc*4;

    const float* xin = x + (long)frame * FRAME_STRIDE;
    const int y  = by*8 + ty;
    const int x0 = bx*32 + tx*4;

    float acc[4][4];
    #pragma unroll
    for (int q=0;q<4;q++)
        #pragma unroll
        for (int px=0;px<4;px++) acc[q][px] = 0.f;

    for (int ci=0; ci<C; ci++){
        // stage input halo tile (34 cols x 10 rows), zero-padded
        for (int i=tid; i<340; i+=256){
            int r  = i/34, cc = i%34;
            int gy = by*8 + r - 1;
            int gx = bx*32 + cc - 1;
            float v = 0.f;
            if (gy>=0 && gy<H && gx>=0 && gx<W)
                v = xin[(ci*H + gy)*W + gx];
            s_in[r][cc] = v;
        }
        // stage weights for 16 c_out of this group, this c_in
        if (tid < 144){
            int col = tid/9, k = tid%9;
            s_w[col][k] = cw[((cog*16+col)*C + ci)*9 + k];
        }
        __syncthreads();

        float rin[3][6];
        #pragma unroll
        for (int dy=0;dy<3;dy++)
            #pragma unroll
            for (int dx=0;dx<6;dx++)
                rin[dy][dx] = s_in[ty+dy][tx*4+dx];

        float rw[4][9];
        #pragma unroll
        for (int q=0;q<4;q++)
            #pragma unroll
            for (int k=0;k<9;k++)
                rw[q][k] = s_w[tc*4+q][k];

        #pragma unroll
        for (int q=0;q<4;q++)
            #pragma unroll
            for (int ky=0;ky<3;ky++)
                #pragma unroll
                for (int kx=0;kx<3;kx++)
                    #pragma unroll
                    for (int px=0;px<4;px++)
                        acc[q][px] = fmaf(rin[ky][px+kx], rw[q][ky*3+kx], acc[q][px]);
        __syncthreads();
    }

    #pragma unroll
    for (int q=0;q<4;q++){
        int co = co_base + q;
        float s  = gamma[co] * rsqrtf(var[co] + 1e-5f);
        float sh = beta[co] - mean[co]*s;
        float b  = cb[co];
        #pragma unroll
        for (int px=0;px<4;px++){
            float v = (acc[q][px] + b)*s + sh;
            g_y[(((long)frame*C + co)*H + y)*W + (x0+px)] = gelu_exact(v);
        }
    }
}

// =====================================================================
// Kernel 2: patch extraction + mask -> d_out patches region
// patches[frame, n, c, i, j] = g_y[frame, c, l*6+i, r*6+j] * mask[i,j]
// with n = l*16 + r (row-major over patch grid).
// =====================================================================
__global__ void patch_kernel(const float* __restrict__ mask,
                             float* __restrict__ out_patches)
{
    int idx = blockIdx.x*256 + threadIdx.x;
    if (idx >= PATCH_ELEMS) return;
    int j = idx % 6;
    int i = (idx/6) % 6;
    int c = (idx/36) % 64;
    int n = (idx/2304) % 256;
    int f = idx / 589824;               // 256*2304
    int l = n >> 4, r = n & 15;
    float v = g_y[(((long)f*C + c)*H + (l*6+i))*W + (r*6+j)];
    out_patches[idx] = v * mask[i*6 + j];
}

// =====================================================================
// Kernel 3: tokens = gelu(A @ Wp^T + bias)
// A = masked patches [8192, 2304] (K-major), Wp [768, 2304] (K-major).
// 64x64 tile, BK=32, 4x4 microtile per thread (256 threads).
// =====================================================================
__global__ __launch_bounds__(256) void gemm_tokens_kernel(
    const float* __restrict__ A,
    const float* __restrict__ Wp,
    const float* __restrict__ bias,
    float* __restrict__ tok)
{
    __shared__ float s_a[32][68];   // [k][m], stride 68 -> 16B-aligned rows
    __shared__ float s_b[32][68];   // [k][n]

    const int tid = threadIdx.x;
    const int bn  = blockIdx.x;     // 0..11
    const int bm  = blockIdx.y;     // 0..127
    const int txx = tid & 15;       // n micro
    const int tyy = tid >> 4;       // m micro

    float acc[4][4];
    #pragma unroll
    for (int im=0;im<4;im++)
        #pragma unroll
        for (int in_=0;in_<4;in_++) acc[im][in_] = 0.f;

    for (int kt=0; kt<FEAT; kt+=32){
        #pragma unroll
        for (int h=0; h<2; h++){
            int li  = tid + h*256;       // 0..511
            int row = li >> 3;           // 0..63
            int kk  = (li & 7) << 2;     // 0,4,...,28
            float4 av = *(const float4*)(A  + (long)(bm*64+row)*FEAT + kt + kk);
            s_a[kk+0][row]=av.x; s_a[kk+1][row]=av.y;
            s_a[kk+2][row]=av.z; s_a[kk+3][row]=av.w;
            float4 bv = *(const float4*)(Wp + (long)(bn*64+row)*FEAT + kt + kk);
            s_b[kk+0][row]=bv.x; s_b[kk+1][row]=bv.y;
            s_b[kk+2][row]=bv.z; s_b[kk+3][row]=bv.w;
        }
        __syncthreads();
        #pragma unroll
        for (int k=0;k<32;k++){
            float4 a4 = *(const float4*)&s_a[k][tyy*4];
            float4 b4 = *(const float4*)&s_b[k][txx*4];
            float am[4] = {a4.x,a4.y,a4.z,a4.w};
            float bv[4] = {b4.x,b4.y,b4.z,b4.w};
            #pragma unroll
            for (int im=0;im<4;im++)
                #pragma unroll
                for (int in_=0;in_<4;in_++)
                    acc[im][in_] = fmaf(am[im], bv[in_], acc[im][in_]);
        }
        __syncthreads();
    }

    #pragma unroll
    for (int im=0;im<4;im++){
        int m = bm*64 + tyy*4 + im;
        #pragma unroll
        for (int in_=0;in_<4;in_++){
            int n = bn*64 + txx*4 + in_;
            tok[(long)m*DIM + n] = gelu_exact(acc[im][in_] + bias[n]);
        }
    }
}

// =====================================================================
extern "C" void kernel_launch(void* const* d_in, const int* in_sizes, int n_in,
                              void* d_out, int out_size)
{
    const float* x      = (const float*)d_in[0];
    const float* conv_w = (const float*)d_in[1];
    const float* conv_b = (const float*)d_in[2];
    const float* gamma  = (const float*)d_in[3];
    const float* beta   = (const float*)d_in[4];
    const float* mean   = (const float*)d_in[5];
    const float* var    = (const float*)d_in[6];
    const float* proj_w = (const float*)d_in[7];
    const float* proj_b = (const float*)d_in[8];
    const float* mask   = (const float*)d_in[9];
    // d_in[10] = patch_size (compile-time constant 6 here)

    float* tokens  = (float*)d_out;                    // [8192, 768]
    float* patches = (float*)d_out + TOK_ELEMS;        // [8192, 2304]

    // 1) conv + bias + BN + GELU
    {
        dim3 grid(3, 12, NF*4);
        conv_bn_gelu_kernel<<<grid, 256>>>(x, conv_w, conv_b,
                                           gamma, beta, mean, var);
    }
    // 2) patch gather + mask
    {
        int blocks = (PATCH_ELEMS + 255) / 256;
        patch_kernel<<<blocks, 256>>>(mask, patches);
    }
    // 3) projection GEMM + bias + GELU (reads masked patches from d_out)
    {
        dim3 grid(DIM/64, M_TOK/64);
        gemm_tokens_kernel<<<grid, 256>>>(patches, proj_w, proj_b, tokens);
    }
}